// round 14
// baseline (speedup 1.0000x reference)
#include <cuda_runtime.h>
#include <cuda_fp16.h>
#include <math.h>
#include <stdint.h>

// Problem constants
#define DM   1024
#define DI   2048
#define DS   16
#define NB   4
#define LLEN 2048
#define NT   8192   // NB * LLEN tokens

// ---------------- scratch (device globals; no allocs allowed) ----------------
// Packed hi/lo layout (per tensor, rows R, inner dim K, RT = rows/tile):
//   half_index = tile*(RT*64) + (row&(RT-1))*64 + ((((k>>3) ^ row) & 7) << 3) + (k&7)
//   tile = (row>>log2RT)*(K>>6) + (k>>6)
// Activations (A operand): RT=128 (16KB tiles). Weights (B operand): RT=64 (8KB tiles).
__device__ float g_xz[NT * (2 * DI)];      // in_proj output (xi | z)
__device__ float g_xi[NT * DI];            // conv+silu output (fp32, for bc/scan)
__device__ float g_delta[NT * DI];         // softplus(dt_proj)
__device__ float g_bc[NT * (2 * DS)];      // (B | C)
__device__ __half g_ahi[NT * DI];          // packed activation hi
__device__ __half g_alo[NT * DI];          // packed activation lo
__device__ __half g_whi[4096 * 1024];      // packed weight hi
__device__ __half g_wlo[4096 * 1024];      // packed weight lo

// ============================ PTX helpers (sm_90 baseline ISA) ===============
__device__ __forceinline__ uint32_t smem_u32(const void* p) {
    uint32_t a;
    asm("{ .reg .u64 t; cvta.to.shared.u64 t, %1; cvt.u32.u64 %0, t; }"
        : "=r"(a) : "l"(p));
    return a;
}
__device__ __forceinline__ void ldsm_x4(uint32_t* r, uint32_t addr) {
    asm volatile("ldmatrix.sync.aligned.m8n8.x4.shared.b16 {%0,%1,%2,%3}, [%4];"
                 : "=r"(r[0]), "=r"(r[1]), "=r"(r[2]), "=r"(r[3]) : "r"(addr));
}
__device__ __forceinline__ void mma16816(float* c, const uint32_t* a, const uint32_t* b) {
    asm volatile("mma.sync.aligned.m16n8k16.row.col.f32.f16.f16.f32 "
                 "{%0,%1,%2,%3}, {%4,%5,%6,%7}, {%8,%9}, {%0,%1,%2,%3};"
                 : "+f"(c[0]), "+f"(c[1]), "+f"(c[2]), "+f"(c[3])
                 : "r"(a[0]), "r"(a[1]), "r"(a[2]), "r"(a[3]), "r"(b[0]), "r"(b[1]));
}
#define MBAR_INIT(addr, cnt) \
    asm volatile("mbarrier.init.shared.b64 [%0], %1;" :: "r"(addr), "r"(cnt) : "memory")
#define MBAR_EXPECT_TX(addr, bytes) \
    asm volatile("mbarrier.arrive.expect_tx.shared.b64 _, [%0], %1;" \
                 :: "r"(addr), "r"(bytes) : "memory")
#define MBAR_WAIT(addr, par) do {                                               \
    uint32_t _m = (addr), _p = (par), _d;                                       \
    asm volatile("{\n\t.reg .pred p;\n\t"                                       \
        "mbarrier.try_wait.parity.acquire.cta.shared::cta.b64 p, [%1], %2;\n\t" \
        "selp.b32 %0, 1, 0, p;\n\t}" : "=r"(_d) : "r"(_m), "r"(_p) : "memory"); \
    if (!_d) {                                                                  \
        asm volatile("{\n\t.reg .pred P1;\n\tWL_%=:\n\t"                        \
            "mbarrier.try_wait.parity.acquire.cta.shared::cta.b64 P1, [%0], %1, 0x989680;\n\t" \
            "@P1 bra.uni WD_%=;\n\tbra.uni WL_%=;\n\tWD_%=:\n\t}"               \
            :: "r"(_m), "r"(_p) : "memory");                                    \
    }                                                                           \
} while (0)
// 1D bulk TMA: global -> shared, completion via mbarrier tx-bytes
#define CP_BULK(dst, src, bytes, mbar) \
    asm volatile("cp.async.bulk.shared::cluster.global.mbarrier::complete_tx::bytes " \
                 "[%0], [%1], %2, [%3];" \
                 :: "r"(dst), "l"(src), "r"(bytes), "r"(mbar) : "memory")

// ==================== generic fp32 -> packed fp16 hi/lo ======================
// kshift = log2(K); rtshift = log2(rows per tile) (7 for A operands, 6 for W).
__global__ __launch_bounds__(256) void split_pack_k(
    const float4* __restrict__ in, __half* __restrict__ hi, __half* __restrict__ lo,
    int kshift, int rtshift, int n4)
{
    int i = blockIdx.x * 256 + threadIdx.x;
    if (i >= n4) return;
    int e   = i << 2;
    int row = e >> kshift;
    int k   = e & ((1 << kshift) - 1);
    float4 v = in[i];
    float x[4] = {v.x, v.y, v.z, v.w};
    __half h[4], l[4];
#pragma unroll
    for (int j = 0; j < 4; j++) {
        h[j] = __float2half_rn(x[j]);
        l[j] = __float2half_rn(x[j] - __half2float(h[j]));
    }
    int tile = (row >> rtshift) * (1 << (kshift - 6)) + (k >> 6);
    size_t idx = (size_t)tile * (64 << rtshift) + (row & ((1 << rtshift) - 1)) * 64
               + ((((k >> 3) ^ row) & 7) << 3) + (k & 7);
    *(uint2*)(hi + idx) = *(uint2*)h;
    *(uint2*)(lo + idx) = *(uint2*)l;
}

// ==================== split-fp16 HMMA NT GEMM (bulk-TMA staged) ==============
// C[m,n] = sum_k A[m,k]*W[n,k];  D = AH*WH + AH*WL + AL*WH  (drops AL*WL)
// Tile 128m x 64n, BK=64. 2-stage TMA pipeline, 48KB/stage, 96KB smem ->
// 2 CTAs/SM. 8 warps as 4m x 2n (warp tile 32x32): fewer LDSM + less smem
// read duplication. Inner loop is TERM-MAJOR so consecutive HMMAs hit
// different accumulators (no acc RAW chains). EPI: 0=none, 1=softplus(v+bias).
template<int EPI>
__global__ __launch_bounds__(256, 2) void hmma_gemm(
    const __half* __restrict__ Ahi, const __half* __restrict__ Alo,
    const __half* __restrict__ Whi, const __half* __restrict__ Wlo,
    const float* __restrict__ bias, float* __restrict__ C,
    int N, int K)
{
    extern __shared__ __align__(128) char smem[];
    __shared__ __align__(8) uint64_t mbars[2];
    const uint32_t sb = smem_u32(smem);
    const int tid  = threadIdx.x;
    const int warp = tid >> 5, lane = tid & 31;
    const int wm = warp >> 1, wn = warp & 1;     // 4m x 2n warp grid
    const int bm = blockIdx.y * 128, bn = blockIdx.x * 64;
    const int iters = K >> 6;

    const uint32_t mb0 = smem_u32(&mbars[0]);
    const uint32_t mb1 = smem_u32(&mbars[1]);
    if (tid == 0) { MBAR_INIT(mb0, 1); MBAR_INIT(mb1, 1); }
    __syncthreads();

    // packed tile bases: A tiles 16KB (128 rows), W tiles 8KB (64 rows)
    const char* srcA_hi = (const char*)Ahi + (size_t)(bm >> 7) * iters * 16384;
    const char* srcA_lo = (const char*)Alo + (size_t)(bm >> 7) * iters * 16384;
    const char* srcW_hi = (const char*)Whi + (size_t)(bn >> 6) * iters * 8192;
    const char* srcW_lo = (const char*)Wlo + (size_t)(bn >> 6) * iters * 8192;

    // stage layout: AH@0(16K) AL@16K(16K) WH@32K(8K) WL@40K(8K); stride 48K
    if (tid == 0) {
#pragma unroll
        for (int s = 0; s < 2; s++) {
            uint32_t mb = s ? mb1 : mb0;
            MBAR_EXPECT_TX(mb, 49152u);
            uint32_t d = sb + (uint32_t)s * 49152u;
            CP_BULK(d,         srcA_hi + (size_t)s * 16384, 16384u, mb);
            CP_BULK(d + 16384, srcA_lo + (size_t)s * 16384, 16384u, mb);
            CP_BULK(d + 32768, srcW_hi + (size_t)s * 8192,  8192u,  mb);
            CP_BULK(d + 40960, srcW_lo + (size_t)s * 8192,  8192u,  mb);
        }
    }

    // ldmatrix lane address components
    const int arow = wm * 32 + (lane & 7) + ((lane >> 3) & 1) * 8;  // + mt*16
    const int ach  = lane >> 4;
    const int brow = wn * 32 + (lane & 7) + ((lane >> 4) & 1) * 8;  // + np*16
    const int bch  = (lane >> 3) & 1;
    const int xr   = lane & 7;

    float acc[2][4][4];   // [mt][nt][quad], warp tile 32m x 32n
#pragma unroll
    for (int mt = 0; mt < 2; mt++)
#pragma unroll
        for (int nt = 0; nt < 4; nt++)
#pragma unroll
            for (int q = 0; q < 4; q++) acc[mt][nt][q] = 0.f;

    int ph0 = 0, ph1 = 0;
    for (int it = 0; it < iters; it++) {
        const int st = it & 1;
        if (st == 0) { MBAR_WAIT(mb0, ph0); ph0 ^= 1; }
        else         { MBAR_WAIT(mb1, ph1); ph1 ^= 1; }

        const uint32_t so = (uint32_t)st * 49152u;
#pragma unroll
        for (int ks = 0; ks < 4; ks++) {
            uint32_t ah[2][4], al[2][4], bh[2][4], bl[2][4];
#pragma unroll
            for (int mt = 0; mt < 2; mt++) {
                uint32_t off = so + (uint32_t)(arow + mt * 16) * 128
                             + ((uint32_t)(((ks << 1) + ach) ^ xr) << 4);
                ldsm_x4(ah[mt], sb + off);
                ldsm_x4(al[mt], sb + 16384 + off);
            }
#pragma unroll
            for (int np = 0; np < 2; np++) {
                uint32_t off = so + 32768 + (uint32_t)(brow + np * 16) * 128
                             + ((uint32_t)(((ks << 1) + bch) ^ xr) << 4);
                ldsm_x4(bh[np], sb + off);
                ldsm_x4(bl[np], sb + 8192 + off);
            }
            // term-major: consecutive MMAs -> different accumulators (no RAW)
#pragma unroll
            for (int mt = 0; mt < 2; mt++)      // term 1: AH*WH
#pragma unroll
                for (int nt = 0; nt < 4; nt++)
                    mma16816(acc[mt][nt], ah[mt], &bh[nt >> 1][(nt & 1) * 2]);
#pragma unroll
            for (int mt = 0; mt < 2; mt++)      // term 2: AH*WL
#pragma unroll
                for (int nt = 0; nt < 4; nt++)
                    mma16816(acc[mt][nt], ah[mt], &bl[nt >> 1][(nt & 1) * 2]);
#pragma unroll
            for (int mt = 0; mt < 2; mt++)      // term 3: AL*WH
#pragma unroll
                for (int nt = 0; nt < 4; nt++)
                    mma16816(acc[mt][nt], al[mt], &bh[nt >> 1][(nt & 1) * 2]);
        }
        __syncthreads();   // all warps done reading stage st
        if (tid == 0 && it + 2 < iters) {
            uint32_t mb = st ? mb1 : mb0;
            MBAR_EXPECT_TX(mb, 49152u);
            uint32_t d = sb + so;
            size_t o16 = (size_t)(it + 2) * 16384;
            size_t o8  = (size_t)(it + 2) * 8192;
            CP_BULK(d,         srcA_hi + o16, 16384u, mb);
            CP_BULK(d + 16384, srcA_lo + o16, 16384u, mb);
            CP_BULK(d + 32768, srcW_hi + o8,  8192u,  mb);
            CP_BULK(d + 40960, srcW_lo + o8,  8192u,  mb);
        }
    }

    // ---- epilogue: fragment -> global (optionally bias + softplus) ----
    const int r0   = bm + wm * 32 + (lane >> 2);
    const int col0 = bn + wn * 32 + (lane & 3) * 2;
#pragma unroll
    for (int mt = 0; mt < 2; mt++) {
#pragma unroll
        for (int nt = 0; nt < 4; nt++) {
            int row = r0 + mt * 16;
            int col = col0 + nt * 8;
            float v[4] = {acc[mt][nt][0], acc[mt][nt][1],
                          acc[mt][nt][2], acc[mt][nt][3]};
            if (EPI == 1) {
                float b0 = bias[col], b1 = bias[col + 1];
                v[0] += b0; v[1] += b1; v[2] += b0; v[3] += b1;
#pragma unroll
                for (int q = 0; q < 4; q++)
                    v[q] = (v[q] > 20.f) ? v[q] : log1pf(__expf(v[q]));
            }
            *(float2*)(C + (size_t)row * N + col)       = make_float2(v[0], v[1]);
            *(float2*)(C + (size_t)(row + 8) * N + col) = make_float2(v[2], v[3]);
        }
    }
}

// ---------- depthwise causal conv (taps=4) + SiLU + fused hi/lo pack ---------
// 4 consecutive channels per thread; writes fp32 xi AND packed hi/lo (K=DI, RT=128).
__global__ __launch_bounds__(256) void conv_silu_pack_k(
    const float* __restrict__ xz, const float4* __restrict__ cw,
    const float* __restrict__ cb, float* __restrict__ xi,
    __half* __restrict__ hi, __half* __restrict__ lo)
{
    int i = blockIdx.x * 256 + threadIdx.x;   // over NT*DI/4
    int e = i << 2;
    int c = e & (DI - 1);
    int t = e >> 11;
    int l = t & (LLEN - 1);
    const float* base = xz + (size_t)(t - l) * (2 * DI) + c;
    float4 w0 = cw[c], w1 = cw[c + 1], w2 = cw[c + 2], w3 = cw[c + 3];
    float4 bz = *(const float4*)(cb + c);
    float acc[4] = {bz.x, bz.y, bz.z, bz.w};
#pragma unroll
    for (int j = 0; j < 4; j++) {
        int ll = l - 3 + j;
        if (ll >= 0) {
            float4 v = *(const float4*)(base + (size_t)ll * (2 * DI));
            acc[0] = fmaf(((const float*)&w0)[j], v.x, acc[0]);
            acc[1] = fmaf(((const float*)&w1)[j], v.y, acc[1]);
            acc[2] = fmaf(((const float*)&w2)[j], v.z, acc[2]);
            acc[3] = fmaf(((const float*)&w3)[j], v.w, acc[3]);
        }
    }
    __half h[4], lw[4];
#pragma unroll
    for (int q = 0; q < 4; q++) {
        acc[q] = acc[q] / (1.f + __expf(-acc[q]));   // silu
        h[q]  = __float2half_rn(acc[q]);
        lw[q] = __float2half_rn(acc[q] - __half2float(h[q]));
    }
    *(float4*)(xi + e) = make_float4(acc[0], acc[1], acc[2], acc[3]);
    int tile = (t >> 7) * 32 + (c >> 6);
    size_t idx = (size_t)tile * 8192 + (t & 127) * 64
               + ((((c >> 3) ^ t) & 7) << 3) + (c & 7);
    *(uint2*)(hi + idx) = *(uint2*)h;
    *(uint2*)(lo + idx) = *(uint2*)lw;
}

// ---------------- x_proj GEMM (N=32): bc[t, 0..31] ---------------------------
__global__ __launch_bounds__(256) void bc_k(const float* __restrict__ xi,
                                            const float* __restrict__ xw,
                                            float* __restrict__ bc)
{
    __shared__ float ws[32][257];
    __shared__ float xs[8][257];
    int tid = threadIdx.x, warp = tid >> 5, lane = tid & 31;
    int tok0 = blockIdx.x * 8;
    float acc = 0.f;
    for (int kc = 0; kc < DI; kc += 256) {
#pragma unroll
        for (int i = 0; i < 32; i++)
            ws[i][tid] = xw[i * DI + kc + tid];
#pragma unroll
        for (int i = 0; i < 8; i++)
            xs[i][tid] = xi[(tok0 + i) * DI + kc + tid];
        __syncthreads();
#pragma unroll 8
        for (int k = 0; k < 256; k++)
            acc = fmaf(xs[warp][k], ws[lane][k], acc);
        __syncthreads();
    }
    bc[(tok0 + warp) * (2 * DS) + lane] = acc;
}

// ---------- selective scan + fused gating + fused hi/lo pack of fin ----------
// Writes fin ONLY as packed fp16 hi/lo (direct A-operand of out_proj GEMM).
__global__ __launch_bounds__(256) void scan_k(
    const float* __restrict__ delta, const float* __restrict__ bc,
    const float* __restrict__ xi,    const float* __restrict__ xz,
    const float* __restrict__ A_log, const float* __restrict__ Dp,
    __half* __restrict__ fhi, __half* __restrict__ flo)
{
    int g = blockIdx.x * 16 + (threadIdx.x >> 4);
    int s = threadIdx.x & 15;
    int b = g >> 11;
    int d = g & (DI - 1);

    float As = -expf(A_log[d * DS + s]);
    float Dd = Dp[d];

    int base_d  = (b * LLEN) * DI + d;
    int base_bc = (b * LLEN) * (2 * DS);
    int base_z  = (b * LLEN) * (2 * DI) + DI + d;
    int t       = b * LLEN;                  // global token index

    float h = 0.f;
    for (int l = 0; l < LLEN; l++) {
        float dl = delta[base_d];
        float xv = xi[base_d];
        float Bt = bc[base_bc + s];
        float Ct = bc[base_bc + DS + s];
        float ab = __expf(dl * As);
        h = fmaf(ab, h, dl * Bt * xv);
        float y = h * Ct;
        y += __shfl_xor_sync(0xffffffffu, y, 1);
        y += __shfl_xor_sync(0xffffffffu, y, 2);
        y += __shfl_xor_sync(0xffffffffu, y, 4);
        y += __shfl_xor_sync(0xffffffffu, y, 8);
        if (s == 0) {
            float zv  = xz[base_z];
            float sig = 1.f / (1.f + __expf(-zv));
            float fv  = (y + xv * Dd) * (zv * sig);
            __half hh = __float2half_rn(fv);
            __half hl = __float2half_rn(fv - __half2float(hh));
            int tile = (t >> 7) * 32 + (d >> 6);
            size_t idx = (size_t)tile * 8192 + (t & 127) * 64
                       + ((((d >> 3) ^ t) & 7) << 3) + (d & 7);
            fhi[idx] = hh;
            flo[idx] = hl;
        }
        base_d  += DI;
        base_bc += 2 * DS;
        base_z  += 2 * DI;
        t++;
    }
}

// ---------------- launch ------------------------------------------------------
extern "C" void kernel_launch(void* const* d_in, const int* in_sizes, int n_in,
                              void* d_out, int out_size)
{
    const float* x          = (const float*)d_in[0];
    const float* in_proj_w  = (const float*)d_in[1];
    const float* conv_w     = (const float*)d_in[2];
    const float* conv_b     = (const float*)d_in[3];
    const float* x_proj_w   = (const float*)d_in[4];
    const float* dt_proj_w  = (const float*)d_in[5];
    const float* dt_proj_b  = (const float*)d_in[6];
    const float* A_log      = (const float*)d_in[7];
    const float* Dvec       = (const float*)d_in[8];
    const float* out_proj_w = (const float*)d_in[9];

    float *xz, *xi, *delta, *bcv;
    __half *ahi, *alo, *whi, *wlo;
    cudaGetSymbolAddress((void**)&xz,    g_xz);
    cudaGetSymbolAddress((void**)&xi,    g_xi);
    cudaGetSymbolAddress((void**)&delta, g_delta);
    cudaGetSymbolAddress((void**)&bcv,   g_bc);
    cudaGetSymbolAddress((void**)&ahi,   g_ahi);
    cudaGetSymbolAddress((void**)&alo,   g_alo);
    cudaGetSymbolAddress((void**)&whi,   g_whi);
    cudaGetSymbolAddress((void**)&wlo,   g_wlo);

    const int SMEM_SZ = 2 * 49152;   // 96 KB: 2 stages x 48KB -> 2 CTAs/SM
    cudaFuncSetAttribute(hmma_gemm<0>, cudaFuncAttributeMaxDynamicSharedMemorySize, SMEM_SZ);
    cudaFuncSetAttribute(hmma_gemm<1>, cudaFuncAttributeMaxDynamicSharedMemorySize, SMEM_SZ);

    // 1) in_proj: x[8192,1024] @ W[4096,1024]^T -> xz
    split_pack_k<<<(NT * DM / 4 + 255) / 256, 256>>>((const float4*)x, ahi, alo, 10, 7, NT * DM / 4);
    split_pack_k<<<(4096 * 1024 / 4 + 255) / 256, 256>>>((const float4*)in_proj_w, whi, wlo, 10, 6, 4096 * 1024 / 4);
    hmma_gemm<0><<<dim3(4096 / 64, NT / 128), 256, SMEM_SZ>>>(
        ahi, alo, whi, wlo, nullptr, xz, 4096, DM);

    // 2) causal depthwise conv + silu -> xi (fp32) + packed hi/lo (for dt GEMM)
    conv_silu_pack_k<<<(NT * DI / 4) / 256, 256>>>(
        xz, (const float4*)conv_w, conv_b, xi, ahi, alo);

    // 3) dt_proj + bias + softplus -> delta
    split_pack_k<<<(DI * DI / 4 + 255) / 256, 256>>>((const float4*)dt_proj_w, whi, wlo, 11, 6, DI * DI / 4);
    hmma_gemm<1><<<dim3(DI / 64, NT / 128), 256, SMEM_SZ>>>(
        ahi, alo, whi, wlo, dt_proj_b, delta, DI, DI);

    // 4) x_proj -> bc (fp32, small N)
    bc_k<<<NT / 8, 256>>>(xi, x_proj_w, bcv);

    // 5) selective scan + gating -> packed fin hi/lo (A operand of out_proj)
    scan_k<<<(NB * DI) / 16, 256>>>(delta, bcv, xi, xz, A_log, Dvec, ahi, alo);

    // 6) out_proj: fin[8192,2048] @ W[1024,2048]^T -> out
    split_pack_k<<<(DM * DI / 4 + 255) / 256, 256>>>((const float4*)out_proj_w, whi, wlo, 11, 6, DM * DI / 4);
    hmma_gemm<0><<<dim3(DM / 64, NT / 128), 256, SMEM_SZ>>>(
        ahi, alo, whi, wlo, nullptr, (float*)d_out, DM, DI);
}

// round 15
// speedup vs baseline: 1.0098x; 1.0098x over previous
#include <cuda_runtime.h>
#include <cuda_fp16.h>
#include <math.h>
#include <stdint.h>

// Problem constants
#define DM   1024
#define DI   2048
#define DS   16
#define NB   4
#define LLEN 2048
#define NT   8192   // NB * LLEN tokens

// ---------------- scratch (device globals; no allocs allowed) ----------------
// Packed hi/lo layout (per tensor, rows R, inner dim K, RT = rows/tile):
//   half_index = tile*(RT*64) + (row&(RT-1))*64 + ((((k>>3) ^ row) & 7) << 3) + (k&7)
//   tile = (row>>log2RT)*(K>>6) + (k>>6)
// Activations (A operand): RT=128 (16KB tiles). Weights (B operand): RT=64 (8KB tiles).
__device__ float g_xz[NT * (2 * DI)];      // in_proj output (xi | z)
__device__ float g_xi[NT * DI];            // conv+silu output (fp32, for bc/scan)
__device__ float g_delta[NT * DI];         // softplus(dt_proj)
__device__ float g_bc[NT * (2 * DS)];      // (B | C)
__device__ __half g_ahi[NT * DI];          // packed activation hi
__device__ __half g_alo[NT * DI];          // packed activation lo
__device__ __half g_whi[4096 * 1024];      // packed weight hi
__device__ __half g_wlo[4096 * 1024];      // packed weight lo

// ============================ PTX helpers (sm_90 baseline ISA) ===============
__device__ __forceinline__ uint32_t smem_u32(const void* p) {
    uint32_t a;
    asm("{ .reg .u64 t; cvta.to.shared.u64 t, %1; cvt.u32.u64 %0, t; }"
        : "=r"(a) : "l"(p));
    return a;
}
__device__ __forceinline__ void ldsm_x4(uint32_t* r, uint32_t addr) {
    asm volatile("ldmatrix.sync.aligned.m8n8.x4.shared.b16 {%0,%1,%2,%3}, [%4];"
                 : "=r"(r[0]), "=r"(r[1]), "=r"(r[2]), "=r"(r[3]) : "r"(addr));
}
__device__ __forceinline__ void mma16816(float* c, const uint32_t* a, const uint32_t* b) {
    asm volatile("mma.sync.aligned.m16n8k16.row.col.f32.f16.f16.f32 "
                 "{%0,%1,%2,%3}, {%4,%5,%6,%7}, {%8,%9}, {%0,%1,%2,%3};"
                 : "+f"(c[0]), "+f"(c[1]), "+f"(c[2]), "+f"(c[3])
                 : "r"(a[0]), "r"(a[1]), "r"(a[2]), "r"(a[3]), "r"(b[0]), "r"(b[1]));
}
#define MBAR_INIT(addr, cnt) \
    asm volatile("mbarrier.init.shared.b64 [%0], %1;" :: "r"(addr), "r"(cnt) : "memory")
#define MBAR_EXPECT_TX(addr, bytes) \
    asm volatile("mbarrier.arrive.expect_tx.shared.b64 _, [%0], %1;" \
                 :: "r"(addr), "r"(bytes) : "memory")
#define MBAR_WAIT(addr, par) do {                                               \
    uint32_t _m = (addr), _p = (par), _d;                                       \
    asm volatile("{\n\t.reg .pred p;\n\t"                                       \
        "mbarrier.try_wait.parity.acquire.cta.shared::cta.b64 p, [%1], %2;\n\t" \
        "selp.b32 %0, 1, 0, p;\n\t}" : "=r"(_d) : "r"(_m), "r"(_p) : "memory"); \
    if (!_d) {                                                                  \
        asm volatile("{\n\t.reg .pred P1;\n\tWL_%=:\n\t"                        \
            "mbarrier.try_wait.parity.acquire.cta.shared::cta.b64 P1, [%0], %1, 0x989680;\n\t" \
            "@P1 bra.uni WD_%=;\n\tbra.uni WL_%=;\n\tWD_%=:\n\t}"               \
            :: "r"(_m), "r"(_p) : "memory");                                    \
    }                                                                           \
} while (0)
// 1D bulk TMA: global -> shared, completion via mbarrier tx-bytes
#define CP_BULK(dst, src, bytes, mbar) \
    asm volatile("cp.async.bulk.shared::cluster.global.mbarrier::complete_tx::bytes " \
                 "[%0], [%1], %2, [%3];" \
                 :: "r"(dst), "l"(src), "r"(bytes), "r"(mbar) : "memory")

// ==================== generic fp32 -> packed fp16 hi/lo ======================
// kshift = log2(K); rtshift = log2(rows per tile) (7 for A operands, 6 for W).
__global__ __launch_bounds__(256) void split_pack_k(
    const float4* __restrict__ in, __half* __restrict__ hi, __half* __restrict__ lo,
    int kshift, int rtshift, int n4)
{
    int i = blockIdx.x * 256 + threadIdx.x;
    if (i >= n4) return;
    int e   = i << 2;
    int row = e >> kshift;
    int k   = e & ((1 << kshift) - 1);
    float4 v = in[i];
    float x[4] = {v.x, v.y, v.z, v.w};
    __half h[4], l[4];
#pragma unroll
    for (int j = 0; j < 4; j++) {
        h[j] = __float2half_rn(x[j]);
        l[j] = __float2half_rn(x[j] - __half2float(h[j]));
    }
    int tile = (row >> rtshift) * (1 << (kshift - 6)) + (k >> 6);
    size_t idx = (size_t)tile * (64 << rtshift) + (row & ((1 << rtshift) - 1)) * 64
               + ((((k >> 3) ^ row) & 7) << 3) + (k & 7);
    *(uint2*)(hi + idx) = *(uint2*)h;
    *(uint2*)(lo + idx) = *(uint2*)l;
}

// ==================== split-fp16 HMMA NT GEMM (bulk-TMA staged) ==============
// C[m,n] = sum_k A[m,k]*W[n,k].
// CTAs with bn < n3:  D = AH*WH + AH*WL + AL*WH  (3-term, ~2^-22 rel err)
// CTAs with bn >= n3: D = AH*WH + AL*WH          (2-term = full-A x W-hi,
//                     ~2.8e-4 rel err; WL tile is never loaded -> less TMA)
// Tile 128m x 64n, BK=64, 2-stage TMA pipeline, 96KB smem -> 2 CTAs/SM.
// 8 warps as 2m x 4n (warp tile 64x16) -- the R12-proven layout.
// EPI: 0=none, 1=softplus(v+bias[n]).
template<int EPI>
__global__ __launch_bounds__(256, 2) void hmma_gemm(
    const __half* __restrict__ Ahi, const __half* __restrict__ Alo,
    const __half* __restrict__ Whi, const __half* __restrict__ Wlo,
    const float* __restrict__ bias, float* __restrict__ C,
    int N, int K, int n3)
{
    extern __shared__ __align__(128) char smem[];
    __shared__ __align__(8) uint64_t mbars[2];
    const uint32_t sb = smem_u32(smem);
    const int tid  = threadIdx.x;
    const int warp = tid >> 5, lane = tid & 31;
    const int wm = warp >> 2, wn = warp & 3;     // 2m x 4n warp grid
    const int bm = blockIdx.y * 128, bn = blockIdx.x * 64;
    const int iters = K >> 6;
    const bool three = (bn < n3);
    const uint32_t stage_bytes = three ? 49152u : 40960u;

    const uint32_t mb0 = smem_u32(&mbars[0]);
    const uint32_t mb1 = smem_u32(&mbars[1]);
    if (tid == 0) { MBAR_INIT(mb0, 1); MBAR_INIT(mb1, 1); }
    __syncthreads();

    // packed tile bases: A tiles 16KB (128 rows), W tiles 8KB (64 rows)
    const char* srcA_hi = (const char*)Ahi + (size_t)(bm >> 7) * iters * 16384;
    const char* srcA_lo = (const char*)Alo + (size_t)(bm >> 7) * iters * 16384;
    const char* srcW_hi = (const char*)Whi + (size_t)(bn >> 6) * iters * 8192;
    const char* srcW_lo = (const char*)Wlo + (size_t)(bn >> 6) * iters * 8192;

    // stage layout: AH@0(16K) AL@16K(16K) WH@32K(8K) WL@40K(8K); stride 48K
    if (tid == 0) {
#pragma unroll
        for (int s = 0; s < 2; s++) {
            uint32_t mb = s ? mb1 : mb0;
            MBAR_EXPECT_TX(mb, stage_bytes);
            uint32_t d = sb + (uint32_t)s * 49152u;
            CP_BULK(d,         srcA_hi + (size_t)s * 16384, 16384u, mb);
            CP_BULK(d + 16384, srcA_lo + (size_t)s * 16384, 16384u, mb);
            CP_BULK(d + 32768, srcW_hi + (size_t)s * 8192,  8192u,  mb);
            if (three)
                CP_BULK(d + 40960, srcW_lo + (size_t)s * 8192, 8192u, mb);
        }
    }

    // ldmatrix lane address components (R12 layout)
    const int arow = wm * 64 + (lane & 7) + ((lane >> 3) & 1) * 8;  // + mt*16
    const int ach  = lane >> 4;
    const int brow = wn * 16 + (lane & 7) + ((lane >> 4) & 1) * 8;
    const int bch  = (lane >> 3) & 1;
    const int xr   = lane & 7;

    float acc[4][2][4];
#pragma unroll
    for (int mt = 0; mt < 4; mt++)
#pragma unroll
        for (int nt = 0; nt < 2; nt++)
#pragma unroll
            for (int q = 0; q < 4; q++) acc[mt][nt][q] = 0.f;

    int ph0 = 0, ph1 = 0;
    for (int it = 0; it < iters; it++) {
        const int st = it & 1;
        if (st == 0) { MBAR_WAIT(mb0, ph0); ph0 ^= 1; }
        else         { MBAR_WAIT(mb1, ph1); ph1 ^= 1; }

        const uint32_t so = (uint32_t)st * 49152u;
#pragma unroll
        for (int ks = 0; ks < 4; ks++) {
            uint32_t ah[4][4], al[4][4], bh[4], bl[4];
#pragma unroll
            for (int mt = 0; mt < 4; mt++) {
                uint32_t off = so + (uint32_t)(arow + mt * 16) * 128
                             + ((uint32_t)(((ks << 1) + ach) ^ xr) << 4);
                ldsm_x4(ah[mt], sb + off);
                ldsm_x4(al[mt], sb + 16384 + off);
            }
            {
                uint32_t off = so + 32768 + (uint32_t)brow * 128
                             + ((uint32_t)(((ks << 1) + bch) ^ xr) << 4);
                ldsm_x4(bh, sb + off);
                if (three) ldsm_x4(bl, sb + 8192 + off);
            }
            if (three) {
#pragma unroll
                for (int mt = 0; mt < 4; mt++)
#pragma unroll
                    for (int t2 = 0; t2 < 2; t2++) {
                        mma16816(acc[mt][t2], ah[mt], &bh[t2 * 2]);
                        mma16816(acc[mt][t2], ah[mt], &bl[t2 * 2]);
                        mma16816(acc[mt][t2], al[mt], &bh[t2 * 2]);
                    }
            } else {
#pragma unroll
                for (int mt = 0; mt < 4; mt++)
#pragma unroll
                    for (int t2 = 0; t2 < 2; t2++) {
                        mma16816(acc[mt][t2], ah[mt], &bh[t2 * 2]);
                        mma16816(acc[mt][t2], al[mt], &bh[t2 * 2]);
                    }
            }
        }
        __syncthreads();   // all warps done reading stage st
        if (tid == 0 && it + 2 < iters) {
            uint32_t mb = st ? mb1 : mb0;
            MBAR_EXPECT_TX(mb, stage_bytes);
            uint32_t d = sb + so;
            size_t o16 = (size_t)(it + 2) * 16384;
            size_t o8  = (size_t)(it + 2) * 8192;
            CP_BULK(d,         srcA_hi + o16, 16384u, mb);
            CP_BULK(d + 16384, srcA_lo + o16, 16384u, mb);
            CP_BULK(d + 32768, srcW_hi + o8,  8192u,  mb);
            if (three)
                CP_BULK(d + 40960, srcW_lo + o8, 8192u, mb);
        }
    }

    // ---- epilogue: fragment -> global (optionally bias + softplus) ----
    const int r0   = bm + wm * 64 + (lane >> 2);
    const int col0 = bn + wn * 16 + (lane & 3) * 2;
#pragma unroll
    for (int mt = 0; mt < 4; mt++) {
#pragma unroll
        for (int nt = 0; nt < 2; nt++) {
            int row = r0 + mt * 16;
            int col = col0 + nt * 8;
            float v[4] = {acc[mt][nt][0], acc[mt][nt][1],
                          acc[mt][nt][2], acc[mt][nt][3]};
            if (EPI == 1) {
                float b0 = bias[col], b1 = bias[col + 1];
                v[0] += b0; v[1] += b1; v[2] += b0; v[3] += b1;
#pragma unroll
                for (int q = 0; q < 4; q++)
                    v[q] = (v[q] > 20.f) ? v[q] : log1pf(__expf(v[q]));
            }
            *(float2*)(C + (size_t)row * N + col)       = make_float2(v[0], v[1]);
            *(float2*)(C + (size_t)(row + 8) * N + col) = make_float2(v[2], v[3]);
        }
    }
}

// ---------- depthwise causal conv (taps=4) + SiLU + fused hi/lo pack ---------
// 4 consecutive channels per thread; writes fp32 xi AND packed hi/lo (K=DI, RT=128).
__global__ __launch_bounds__(256) void conv_silu_pack_k(
    const float* __restrict__ xz, const float4* __restrict__ cw,
    const float* __restrict__ cb, float* __restrict__ xi,
    __half* __restrict__ hi, __half* __restrict__ lo)
{
    int i = blockIdx.x * 256 + threadIdx.x;   // over NT*DI/4
    int e = i << 2;
    int c = e & (DI - 1);
    int t = e >> 11;
    int l = t & (LLEN - 1);
    const float* base = xz + (size_t)(t - l) * (2 * DI) + c;
    float4 w0 = cw[c], w1 = cw[c + 1], w2 = cw[c + 2], w3 = cw[c + 3];
    float4 bz = *(const float4*)(cb + c);
    float acc[4] = {bz.x, bz.y, bz.z, bz.w};
#pragma unroll
    for (int j = 0; j < 4; j++) {
        int ll = l - 3 + j;
        if (ll >= 0) {
            float4 v = *(const float4*)(base + (size_t)ll * (2 * DI));
            acc[0] = fmaf(((const float*)&w0)[j], v.x, acc[0]);
            acc[1] = fmaf(((const float*)&w1)[j], v.y, acc[1]);
            acc[2] = fmaf(((const float*)&w2)[j], v.z, acc[2]);
            acc[3] = fmaf(((const float*)&w3)[j], v.w, acc[3]);
        }
    }
    __half h[4], lw[4];
#pragma unroll
    for (int q = 0; q < 4; q++) {
        acc[q] = acc[q] / (1.f + __expf(-acc[q]));   // silu
        h[q]  = __float2half_rn(acc[q]);
        lw[q] = __float2half_rn(acc[q] - __half2float(h[q]));
    }
    *(float4*)(xi + e) = make_float4(acc[0], acc[1], acc[2], acc[3]);
    int tile = (t >> 7) * 32 + (c >> 6);
    size_t idx = (size_t)tile * 8192 + (t & 127) * 64
               + ((((c >> 3) ^ t) & 7) << 3) + (c & 7);
    *(uint2*)(hi + idx) = *(uint2*)h;
    *(uint2*)(lo + idx) = *(uint2*)lw;
}

// ---------------- x_proj GEMM (N=32): bc[t, 0..31] ---------------------------
// 32 tokens per block (4x less weight re-staging than 8-token version).
// Thread (warp w, lane n) accumulates 4 tokens {w, w+8, w+16, w+24} x column n.
// smem [32][133]: (lane*133+k)&31 = (lane*5+k)&31, 5 coprime 32 -> conflict-free.
__global__ __launch_bounds__(256) void bc_k(const float* __restrict__ xi,
                                            const float* __restrict__ xw,
                                            float* __restrict__ bc)
{
    __shared__ float ws[32][133];
    __shared__ float xs[32][133];
    int tid = threadIdx.x, warp = tid >> 5, lane = tid & 31;
    int tok0 = blockIdx.x * 32;
    float acc[4] = {0.f, 0.f, 0.f, 0.f};
    for (int kc = 0; kc < DI; kc += 128) {
#pragma unroll
        for (int i = 0; i < 16; i++) {          // 32 rows x 128 cols, 4096 elems
            int idx = i * 256 + tid;
            int row = idx >> 7, col = idx & 127;
            ws[row][col] = xw[row * DI + kc + col];
            xs[row][col] = xi[(size_t)(tok0 + row) * DI + kc + col];
        }
        __syncthreads();
#pragma unroll 4
        for (int k = 0; k < 128; k++) {
            float wv = ws[lane][k];
            acc[0] = fmaf(xs[warp][k],      wv, acc[0]);
            acc[1] = fmaf(xs[warp + 8][k],  wv, acc[1]);
            acc[2] = fmaf(xs[warp + 16][k], wv, acc[2]);
            acc[3] = fmaf(xs[warp + 24][k], wv, acc[3]);
        }
        __syncthreads();
    }
#pragma unroll
    for (int q = 0; q < 4; q++)
        bc[(size_t)(tok0 + warp + q * 8) * (2 * DS) + lane] = acc[q];
}

// ---------- selective scan + fused gating + fused hi/lo pack of fin ----------
// Writes fin ONLY as packed fp16 hi/lo (direct A-operand of out_proj GEMM).
__global__ __launch_bounds__(256) void scan_k(
    const float* __restrict__ delta, const float* __restrict__ bc,
    const float* __restrict__ xi,    const float* __restrict__ xz,
    const float* __restrict__ A_log, const float* __restrict__ Dp,
    __half* __restrict__ fhi, __half* __restrict__ flo)
{
    int g = blockIdx.x * 16 + (threadIdx.x >> 4);
    int s = threadIdx.x & 15;
    int b = g >> 11;
    int d = g & (DI - 1);

    float As = -expf(A_log[d * DS + s]);
    float Dd = Dp[d];

    int base_d  = (b * LLEN) * DI + d;
    int base_bc = (b * LLEN) * (2 * DS);
    int base_z  = (b * LLEN) * (2 * DI) + DI + d;
    int t       = b * LLEN;                  // global token index

    float h = 0.f;
    for (int l = 0; l < LLEN; l++) {
        float dl = delta[base_d];
        float xv = xi[base_d];
        float Bt = bc[base_bc + s];
        float Ct = bc[base_bc + DS + s];
        float ab = __expf(dl * As);
        h = fmaf(ab, h, dl * Bt * xv);
        float y = h * Ct;
        y += __shfl_xor_sync(0xffffffffu, y, 1);
        y += __shfl_xor_sync(0xffffffffu, y, 2);
        y += __shfl_xor_sync(0xffffffffu, y, 4);
        y += __shfl_xor_sync(0xffffffffu, y, 8);
        if (s == 0) {
            float zv  = xz[base_z];
            float sig = 1.f / (1.f + __expf(-zv));
            float fv  = (y + xv * Dd) * (zv * sig);
            __half hh = __float2half_rn(fv);
            __half hl = __float2half_rn(fv - __half2float(hh));
            int tile = (t >> 7) * 32 + (d >> 6);
            size_t idx = (size_t)tile * 8192 + (t & 127) * 64
                       + ((((d >> 3) ^ t) & 7) << 3) + (d & 7);
            fhi[idx] = hh;
            flo[idx] = hl;
        }
        base_d  += DI;
        base_bc += 2 * DS;
        base_z  += 2 * DI;
        t++;
    }
}

// ---------------- launch ------------------------------------------------------
extern "C" void kernel_launch(void* const* d_in, const int* in_sizes, int n_in,
                              void* d_out, int out_size)
{
    const float* x          = (const float*)d_in[0];
    const float* in_proj_w  = (const float*)d_in[1];
    const float* conv_w     = (const float*)d_in[2];
    const float* conv_b     = (const float*)d_in[3];
    const float* x_proj_w   = (const float*)d_in[4];
    const float* dt_proj_w  = (const float*)d_in[5];
    const float* dt_proj_b  = (const float*)d_in[6];
    const float* A_log      = (const float*)d_in[7];
    const float* Dvec       = (const float*)d_in[8];
    const float* out_proj_w = (const float*)d_in[9];

    float *xz, *xi, *delta, *bcv;
    __half *ahi, *alo, *whi, *wlo;
    cudaGetSymbolAddress((void**)&xz,    g_xz);
    cudaGetSymbolAddress((void**)&xi,    g_xi);
    cudaGetSymbolAddress((void**)&delta, g_delta);
    cudaGetSymbolAddress((void**)&bcv,   g_bc);
    cudaGetSymbolAddress((void**)&ahi,   g_ahi);
    cudaGetSymbolAddress((void**)&alo,   g_alo);
    cudaGetSymbolAddress((void**)&whi,   g_whi);
    cudaGetSymbolAddress((void**)&wlo,   g_wlo);

    const int SMEM_SZ = 2 * 49152;   // 96 KB: 2 stages x 48KB -> 2 CTAs/SM
    cudaFuncSetAttribute(hmma_gemm<0>, cudaFuncAttributeMaxDynamicSharedMemorySize, SMEM_SZ);
    cudaFuncSetAttribute(hmma_gemm<1>, cudaFuncAttributeMaxDynamicSharedMemorySize, SMEM_SZ);

    // 1) in_proj: x[8192,1024] @ W[4096,1024]^T -> xz
    //    xi-columns [0,2048) 3-term; z-columns [2048,4096) 2-term (gate path).
    split_pack_k<<<(NT * DM / 4 + 255) / 256, 256>>>((const float4*)x, ahi, alo, 10, 7, NT * DM / 4);
    split_pack_k<<<(4096 * 1024 / 4 + 255) / 256, 256>>>((const float4*)in_proj_w, whi, wlo, 10, 6, 4096 * 1024 / 4);
    hmma_gemm<0><<<dim3(4096 / 64, NT / 128), 256, SMEM_SZ>>>(
        ahi, alo, whi, wlo, nullptr, xz, 4096, DM, 2048);

    // 2) causal depthwise conv + silu -> xi (fp32) + packed hi/lo (for dt GEMM)
    conv_silu_pack_k<<<(NT * DI / 4) / 256, 256>>>(
        xz, (const float4*)conv_w, conv_b, xi, ahi, alo);

    // 3) dt_proj + bias + softplus -> delta (3-term: scan amplifies errors)
    split_pack_k<<<(DI * DI / 4 + 255) / 256, 256>>>((const float4*)dt_proj_w, whi, wlo, 11, 6, DI * DI / 4);
    hmma_gemm<1><<<dim3(DI / 64, NT / 128), 256, SMEM_SZ>>>(
        ahi, alo, whi, wlo, dt_proj_b, delta, DI, DI, DI);

    // 4) x_proj -> bc (fp32, small N)
    bc_k<<<NT / 32, 256>>>(xi, x_proj_w, bcv);

    // 5) selective scan + gating -> packed fin hi/lo (A operand of out_proj)
    scan_k<<<(NB * DI) / 16, 256>>>(delta, bcv, xi, xz, A_log, Dvec, ahi, alo);

    // 6) out_proj: fin[8192,2048] @ W[1024,2048]^T -> out (2-term, direct path)
    split_pack_k<<<(DM * DI / 4 + 255) / 256, 256>>>((const float4*)out_proj_w, whi, wlo, 11, 6, DM * DI / 4);
    hmma_gemm<0><<<dim3(DM / 64, NT / 128), 256, SMEM_SZ>>>(
        ahi, alo, whi, wlo, nullptr, (float*)d_out, DM, DI, 0);
}